// round 12
// baseline (speedup 1.0000x reference)
#include <cuda_runtime.h>

// MaxPool3d k=2 s=2 fp32 [2,32,128,128,128] -> [2,32,64,64,64]
// FINAL = R4 best (wall 88.1us, kernel 83.4us, 6997 GB/s = 88.3% HBM spec).
// block=512, exact grid (no tail guard), 4 outputs/thread along W,
// 8x float4 streaming loads (__ldcs), 1x float4 streaming store (__stcs).
//
// Measured knob matrix (all within +-1.3us noise unless noted):
//   ILP 4->8 outputs/thread ......... flat
//   persistent single-wave .......... -12% (L1 pressure + loop bubbles)
//   tail-guard removal .............. +1.5% (this kernel)
//   block 256 vs 512 ................ flat
//   __stwt write-through ............ -7% (defeats L2 write coalescing)
//   256-bit LDG (ld.v8.f32) ......... flat (same DRAM%, fewer regs-occ)
// DRAM utilization is invariant 57%-83% occupancy -> LTS/HBM path is the
// ceiling at ~88% of spec for this 9:1 read:write stream. Converged.

#define W_IN    128
#define HW_IN   (128 * 128)
#define DHW_IN  (128 * 128 * 128)
#define W_OUT   64
#define HW_OUT  (64 * 64)
#define DHW_OUT (64 * 64 * 64)

__global__ void __launch_bounds__(512) maxpool3d_k2s2_final(
    const float* __restrict__ in, float* __restrict__ out)
{
    int tid = blockIdx.x * blockDim.x + threadIdx.x;   // exact grid: no bounds check

    // tid -> (bc, d, h, q), q in [0,16): outputs w = 4q..4q+3
    int q  = tid & 15;
    int t1 = tid >> 4;
    int h  = t1 & 63;
    int t2 = t1 >> 6;
    int d  = t2 & 63;
    int bc = t2 >> 6;            // 0..63

    const float4* base = reinterpret_cast<const float4*>(
        in + (size_t)bc * DHW_IN + (size_t)(2 * d) * HW_IN + (size_t)(2 * h) * W_IN)
        + 2 * q;

    float4 r0a = __ldcs(base);
    float4 r0b = __ldcs(base + 1);
    float4 r1a = __ldcs(base + (W_IN / 4));
    float4 r1b = __ldcs(base + (W_IN / 4) + 1);
    float4 r2a = __ldcs(base + (HW_IN / 4));
    float4 r2b = __ldcs(base + (HW_IN / 4) + 1);
    float4 r3a = __ldcs(base + (HW_IN / 4 + W_IN / 4));
    float4 r3b = __ldcs(base + (HW_IN / 4 + W_IN / 4) + 1);

    float4 res;
    res.x = fmaxf(fmaxf(fmaxf(r0a.x, r0a.y), fmaxf(r1a.x, r1a.y)),
                  fmaxf(fmaxf(r2a.x, r2a.y), fmaxf(r3a.x, r3a.y)));
    res.y = fmaxf(fmaxf(fmaxf(r0a.z, r0a.w), fmaxf(r1a.z, r1a.w)),
                  fmaxf(fmaxf(r2a.z, r2a.w), fmaxf(r3a.z, r3a.w)));
    res.z = fmaxf(fmaxf(fmaxf(r0b.x, r0b.y), fmaxf(r1b.x, r1b.y)),
                  fmaxf(fmaxf(r2b.x, r2b.y), fmaxf(r3b.x, r3b.y)));
    res.w = fmaxf(fmaxf(fmaxf(r0b.z, r0b.w), fmaxf(r1b.z, r1b.w)),
                  fmaxf(fmaxf(r2b.z, r2b.w), fmaxf(r3b.z, r3b.w)));

    float4* op = reinterpret_cast<float4*>(
        out + (size_t)bc * DHW_OUT + (size_t)d * HW_OUT + (size_t)h * W_OUT) + q;
    __stcs(op, res);
}

extern "C" void kernel_launch(void* const* d_in, const int* in_sizes, int n_in,
                              void* d_out, int out_size)
{
    const float* in = (const float*)d_in[0];
    float* out = (float*)d_out;
    int n_quads = out_size / 4;              // 4,194,304 (divides 512 exactly)
    maxpool3d_k2s2_final<<<n_quads / 512, 512>>>(in, out);
}